// round 16
// baseline (speedup 1.0000x reference)
#include <cuda_runtime.h>
#include <cuda_fp16.h>
#include <math.h>

// Accumulators (no allocations allowed; device globals, zero-initialized).
__device__ double g_sum[8];           // spread partial sums
__device__ unsigned int g_tick;       // completion counter (self-wrapping)

constexpr int TILE    = 512;   // brick edge; T=16 -> 136 blocks = one wave
constexpr int THREADS = 512;   // one i row per thread

// fp16x2 per-half sign flip: a ^ (b & 0x80008000)  (one LOP3)
__device__ __forceinline__ unsigned int sflip2(unsigned int a, unsigned int b) {
    unsigned int r;
    asm("lop3.b32 %0, %1, %2, %3, 0x78;"
        : "=r"(r) : "r"(a), "r"(b), "n"(0x80008000u));
    return r;
}
__device__ __forceinline__ __half2 u2h(unsigned int u) {
    __half2 h; *reinterpret_cast<unsigned int*>(&h) = u; return h;
}
__device__ __forceinline__ unsigned int h2u(__half2 h) {
    return *reinterpret_cast<unsigned int*>(&h);
}

// ---------------------------------------------------------------------------
// ONE kernel, 512x512 triangle bricks, T*(T+1)/2 = 136 blocks = one wave:
//   * per-block prep: thread t computes {d^2,e} for its i row (registers,
//     exact fp32) and its j row (-> fp16 smem). No second launch, no
//     cross-block sync (R9/R12: any in-kernel grid sync serializes).
//     Pad rows {+inf, 60000} -> every pad-involving slot nets 0 (nslots).
//   * pair value: relu(x+1) = max(x,-1)+1, x = sign(d2_j-d2_i)*(e_i-e_j)
//     via per-half sign-bit XOR (LOP3).
//   * DUAL-STREAM fp16x2 loop: j-vectors s and s+32 per iter -> 16 pairs,
//     8 independent acc chains, software-pipelined LDS.128 prefetch,
//     fp32 spill every 8 iters (safer than validated 16-iter cadence).
//   * single code path incl. diagonal: unmasked ordered loop counts each
//     unordered pair twice on diag bricks (self-pairs exactly 0) -> x0.5.
//   * spread 8-slot double atomics; last block (g_tick) gathers + writes
//     out[0]; all counters self-reset (graph-replayable).
// ---------------------------------------------------------------------------
__global__ __launch_bounds__(THREADS) void fused_kernel(
    const float* __restrict__ energies,
    const float* __restrict__ pv,
    const float* __restrict__ pt,
    int B, int P, int T, int NB, double nslots, double invcnt,
    float* __restrict__ out)
{
    int t   = threadIdx.x;
    int bid = blockIdx.x;

    // --- triangle decode: bid -> (ti, tj), ti <= tj ---
    float tf = 2.0f * T + 1.0f;
    int ti = (int)floorf((tf - sqrtf(fmaxf(tf * tf - 8.0f * (float)bid, 0.0f))) * 0.5f);
    if (ti < 0) ti = 0;
    if (ti > T - 1) ti = T - 1;
    while (ti > 0 && (ti * T - ti * (ti - 1) / 2) > bid) ti--;
    while (((ti + 1) * T - (ti + 1) * ti / 2) <= bid) ti++;
    int tj = ti + (bid - (ti * T - ti * (ti - 1) / 2));
    bool diag = (ti == tj);

    __shared__ __half jd[TILE];          // fp16 d^2   (1 KB)
    __shared__ __half je[TILE];          // fp16 -e    (1 KB)
    __shared__ float  ssum[THREADS / 32];

    // --- in-block prep: {d^2, e} for one row ---
    auto row_de = [&](int row) -> float2 {
        if (row >= B) return make_float2(INFINITY, 60000.0f);   // pad row
        float s = 0.0f;
        if (P == 16) {
            const float4* pv4 = (const float4*)(pv + (size_t)row * 16);
            const float4* pt4 = (const float4*)pt;
            #pragma unroll
            for (int q = 0; q < 4; q++) {
                float4 v = pv4[q];
                float4 w = pt4[q];
                float a = v.x - w.x, b = v.y - w.y;
                float c = v.z - w.z, d = v.w - w.w;
                s = fmaf(a, a, fmaf(b, b, fmaf(c, c, fmaf(d, d, s))));
            }
        } else {
            for (int q = 0; q < P; q++) {
                float df = pv[(size_t)row * P + q] - pt[q];
                s = fmaf(df, df, s);
            }
        }
        return make_float2(s, energies[row]);
    };

    float2 mi = row_de(ti * TILE + t);                 // my i row (exact)
    float2 mj = diag ? mi : row_de(tj * TILE + t);     // my j row
    jd[t] = __float2half_rn(mj.x);
    je[t] = __float2half_rn(-mj.y);
    __syncthreads();

    unsigned int ndi2 = h2u(__float2half2_rn(-mi.x));   // (-d2_i, -d2_i)
    unsigned int ei2  = h2u(__float2half2_rn(mi.y));    // ( e_i ,  e_i )
    const __half2 neg1 = __floats2half2_rn(-1.0f, -1.0f);

    const uint4* jd4 = (const uint4*)jd;   // 64 uint4 (8 halves each)
    const uint4* je4 = (const uint4*)je;

    float facc = 0.0f;

    // ---- dual-stream unmasked loop: 16 pairs / iter, 32 iters ----
    uint4 qda = jd4[0],  qea = je4[0];     // stream A: idx 0..31
    uint4 qdb = jd4[32], qeb = je4[32];    // stream B: idx 32..63
    #pragma unroll
    for (int kk = 0; kk < 4; kk++) {                 // fp32 spill chunks
        __half2 a0 = u2h(0u), a1 = u2h(0u), a2 = u2h(0u), a3 = u2h(0u);
        __half2 b0 = u2h(0u), b1 = u2h(0u), b2 = u2h(0u), b3 = u2h(0u);
        #pragma unroll
        for (int u = 0; u < 8; u++) {
            int lin = kk * 8 + u;
            uint4 nda, nea, ndb, neb;
            if (lin < 31) {                          // prefetch next
                nda = jd4[lin + 1];  nea = je4[lin + 1];
                ndb = jd4[lin + 33]; neb = je4[lin + 33];
            }
            // stream A
            unsigned int da0 = h2u(__hadd2(u2h(qda.x), u2h(ndi2)));
            unsigned int da1 = h2u(__hadd2(u2h(qda.y), u2h(ndi2)));
            unsigned int da2 = h2u(__hadd2(u2h(qda.z), u2h(ndi2)));
            unsigned int da3 = h2u(__hadd2(u2h(qda.w), u2h(ndi2)));
            unsigned int ea0 = h2u(__hadd2(u2h(ei2), u2h(qea.x)));
            unsigned int ea1 = h2u(__hadd2(u2h(ei2), u2h(qea.y)));
            unsigned int ea2 = h2u(__hadd2(u2h(ei2), u2h(qea.z)));
            unsigned int ea3 = h2u(__hadd2(u2h(ei2), u2h(qea.w)));
            a0 = __hadd2(a0, __hmax2(u2h(sflip2(ea0, da0)), neg1));
            a1 = __hadd2(a1, __hmax2(u2h(sflip2(ea1, da1)), neg1));
            a2 = __hadd2(a2, __hmax2(u2h(sflip2(ea2, da2)), neg1));
            a3 = __hadd2(a3, __hmax2(u2h(sflip2(ea3, da3)), neg1));
            // stream B
            unsigned int db0 = h2u(__hadd2(u2h(qdb.x), u2h(ndi2)));
            unsigned int db1 = h2u(__hadd2(u2h(qdb.y), u2h(ndi2)));
            unsigned int db2 = h2u(__hadd2(u2h(qdb.z), u2h(ndi2)));
            unsigned int db3 = h2u(__hadd2(u2h(qdb.w), u2h(ndi2)));
            unsigned int eb0 = h2u(__hadd2(u2h(ei2), u2h(qeb.x)));
            unsigned int eb1 = h2u(__hadd2(u2h(ei2), u2h(qeb.y)));
            unsigned int eb2 = h2u(__hadd2(u2h(ei2), u2h(qeb.z)));
            unsigned int eb3 = h2u(__hadd2(u2h(ei2), u2h(qeb.w)));
            b0 = __hadd2(b0, __hmax2(u2h(sflip2(eb0, db0)), neg1));
            b1 = __hadd2(b1, __hmax2(u2h(sflip2(eb1, db1)), neg1));
            b2 = __hadd2(b2, __hmax2(u2h(sflip2(eb2, db2)), neg1));
            b3 = __hadd2(b3, __hmax2(u2h(sflip2(eb3, db3)), neg1));
            qda = nda; qea = nea; qdb = ndb; qeb = neb;
        }
        float2 fa0 = __half22float2(a0), fa1 = __half22float2(a1);
        float2 fa2 = __half22float2(a2), fa3 = __half22float2(a3);
        float2 fb0 = __half22float2(b0), fb1 = __half22float2(b1);
        float2 fb2 = __half22float2(b2), fb3 = __half22float2(b3);
        facc += (((fa0.x + fa0.y) + (fa1.x + fa1.y))
               + ((fa2.x + fa2.y) + (fa3.x + fa3.y)))
              + (((fb0.x + fb0.y) + (fb1.x + fb1.y))
               + ((fb2.x + fb2.y) + (fb3.x + fb3.y)));
    }

    // diagonal brick counted every unordered pair twice (self-pairs = 0)
    if (diag) facc *= 0.5f;

    // --- block reduction ---
    #pragma unroll
    for (int o = 16; o > 0; o >>= 1)
        facc += __shfl_down_sync(0xFFFFFFFFu, facc, o);

    int w = t >> 5, l = t & 31;
    if (l == 0) ssum[w] = facc;
    __syncthreads();

    // --- spread global accumulation + last-block epilogue ---
    if (t == 0) {
        float a = 0.0f;
        #pragma unroll
        for (int k = 0; k < THREADS / 32; k++) a += ssum[k];
        atomicAdd(&g_sum[bid & 7], (double)a);     // 8 slots -> no burst
        __threadfence();
        unsigned int old = atomicInc(&g_tick, (unsigned int)(NB - 1));
        if (old == (unsigned int)(NB - 1)) {
            __threadfence();
            double tot = 0.0;
            #pragma unroll
            for (int k = 0; k < 8; k++) {
                unsigned long long b =
                    atomicExch((unsigned long long*)&g_sum[k], 0ull);
                tot += __longlong_as_double(b);    // read + reset (replayable)
            }
            out[0] = (float)((tot + nslots) * invcnt);
        }
    }
}

// ---------------------------------------------------------------------------
extern "C" void kernel_launch(void* const* d_in, const int* in_sizes, int n_in,
                              void* d_out, int out_size) {
    const float* energies = (const float*)d_in[0];   // (B, 1)
    const float* pv       = (const float*)d_in[1];   // (B, P)
    const float* pt       = (const float*)d_in[2];   // (P,)
    float* out            = (float*)d_out;

    int B = in_sizes[0];
    int P = in_sizes[2];

    int T  = (B + TILE - 1) / TILE;
    int NB = T * (T + 1) / 2;

    // exact +1-per-slot total (unordered slots):
    //   off-diag bricks: TILE*TILE each; diag: TILE*(TILE-1)/2 each;
    //   pad rows net 0 except pad-pad slots (value 0 but +1) -> subtract.
    double npad = (double)(T * TILE - B);
    double nslots = (double)(T * (T - 1) / 2) * (double)TILE * (double)TILE
                  + (double)T * (double)((long long)TILE * (TILE - 1) / 2)
                  - npad * (npad - 1.0) * 0.5;

    double cnt = (double)B * (double)(B - 1) * 0.5;
    if (cnt < 1.0) cnt = 1.0;

    fused_kernel<<<NB, THREADS>>>(energies, pv, pt, B, P, T, NB,
                                  nslots, 1.0 / cnt, out);
}

// round 17
// speedup vs baseline: 1.0175x; 1.0175x over previous
#include <cuda_runtime.h>
#include <cuda_fp16.h>
#include <math.h>

// Accumulators (no allocations allowed; device globals, zero-initialized).
__device__ double g_sum[8];           // spread partial sums
__device__ unsigned int g_tick;       // completion counter (self-wrapping)

constexpr int TILE    = 512;   // brick edge; T=16 -> 136 blocks = one wave
constexpr int THREADS = 512;   // one i row per thread

// fp16x2 per-half sign flip: a ^ (b & 0x80008000)  (one LOP3)
__device__ __forceinline__ unsigned int sflip2(unsigned int a, unsigned int b) {
    unsigned int r;
    asm("lop3.b32 %0, %1, %2, %3, 0x78;"
        : "=r"(r) : "r"(a), "r"(b), "n"(0x80008000u));
    return r;
}
__device__ __forceinline__ __half2 u2h(unsigned int u) {
    __half2 h; *reinterpret_cast<unsigned int*>(&h) = u; return h;
}
__device__ __forceinline__ unsigned int h2u(__half2 h) {
    return *reinterpret_cast<unsigned int*>(&h);
}

// ---------------------------------------------------------------------------
// ONE kernel, 512x512 triangle bricks, T*(T+1)/2 = 136 blocks = one wave:
//   * per-block prep: thread t computes {d^2,e} for its i row (registers,
//     exact fp32) and its j row (-> fp16 smem). Single launch, no cross-
//     block sync (R9/R12: any in-kernel grid sync serializes).
//     Pad rows {+inf, 60000} -> every pad-involving slot nets 0 (nslots).
//   * pair value: relu(x+1) = max(x,-1)+1, x = sign(d2_j-d2_i)*(e_i-e_j)
//     via per-half sign-bit XOR (LOP3).
//   * loop = R15's validated single-stream fp16x2 form: 8 pairs/iter
//     (2 broadcast LDS.128 + 16 fp16x2 ops), software-pipelined prefetch,
//     4 acc chains, fp32 spill every 16 iters (rel_err ~2e-6 validated).
//   * single code path incl. diagonal: unmasked ordered loop counts each
//     unordered pair twice on diag bricks (self-pairs exactly 0) -> x0.5.
//   * spread 8-slot double atomics; last block (g_tick) gathers + writes
//     out[0]; all counters self-reset (graph-replayable).
// ---------------------------------------------------------------------------
__global__ __launch_bounds__(THREADS) void fused_kernel(
    const float* __restrict__ energies,
    const float* __restrict__ pv,
    const float* __restrict__ pt,
    int B, int P, int T, int NB, double nslots, double invcnt,
    float* __restrict__ out)
{
    int t   = threadIdx.x;
    int bid = blockIdx.x;

    // --- triangle decode: bid -> (ti, tj), ti <= tj ---
    float tf = 2.0f * T + 1.0f;
    int ti = (int)floorf((tf - sqrtf(fmaxf(tf * tf - 8.0f * (float)bid, 0.0f))) * 0.5f);
    if (ti < 0) ti = 0;
    if (ti > T - 1) ti = T - 1;
    while (ti > 0 && (ti * T - ti * (ti - 1) / 2) > bid) ti--;
    while (((ti + 1) * T - (ti + 1) * ti / 2) <= bid) ti++;
    int tj = ti + (bid - (ti * T - ti * (ti - 1) / 2));
    bool diag = (ti == tj);

    __shared__ __half jd[TILE];          // fp16 d^2   (1 KB)
    __shared__ __half je[TILE];          // fp16 -e    (1 KB)
    __shared__ float  ssum[THREADS / 32];

    // --- in-block prep: {d^2, e} for one row ---
    auto row_de = [&](int row) -> float2 {
        if (row >= B) return make_float2(INFINITY, 60000.0f);   // pad row
        float s = 0.0f;
        if (P == 16) {
            const float4* pv4 = (const float4*)(pv + (size_t)row * 16);
            const float4* pt4 = (const float4*)pt;
            #pragma unroll
            for (int q = 0; q < 4; q++) {
                float4 v = pv4[q];
                float4 w = pt4[q];
                float a = v.x - w.x, b = v.y - w.y;
                float c = v.z - w.z, d = v.w - w.w;
                s = fmaf(a, a, fmaf(b, b, fmaf(c, c, fmaf(d, d, s))));
            }
        } else {
            for (int q = 0; q < P; q++) {
                float df = pv[(size_t)row * P + q] - pt[q];
                s = fmaf(df, df, s);
            }
        }
        return make_float2(s, energies[row]);
    };

    float2 mi = row_de(ti * TILE + t);                 // my i row (exact)
    float2 mj = diag ? mi : row_de(tj * TILE + t);     // my j row
    jd[t] = __float2half_rn(mj.x);
    je[t] = __float2half_rn(-mj.y);
    __syncthreads();

    unsigned int ndi2 = h2u(__float2half2_rn(-mi.x));   // (-d2_i, -d2_i)
    unsigned int ei2  = h2u(__float2half2_rn(mi.y));    // ( e_i ,  e_i )
    const __half2 neg1 = __floats2half2_rn(-1.0f, -1.0f);

    const uint4* jd4 = (const uint4*)jd;   // 64 uint4 (8 halves each)
    const uint4* je4 = (const uint4*)je;

    float facc = 0.0f;

    // ---- R15 loop: 8 pairs / iter, 64 iters, 4 spill chunks ----
    uint4 qd = jd4[0], qe = je4[0];
    #pragma unroll
    for (int kk = 0; kk < 4; kk++) {                 // fp32 spill chunks
        __half2 a0 = u2h(0u), a1 = u2h(0u), a2 = u2h(0u), a3 = u2h(0u);
        #pragma unroll
        for (int u = 0; u < 16; u++) {
            int idx = kk * 16 + u;
            uint4 nd, ne;
            if (idx < 63) { nd = jd4[idx + 1]; ne = je4[idx + 1]; }
            unsigned int dd0 = h2u(__hadd2(u2h(qd.x), u2h(ndi2)));
            unsigned int dd1 = h2u(__hadd2(u2h(qd.y), u2h(ndi2)));
            unsigned int dd2 = h2u(__hadd2(u2h(qd.z), u2h(ndi2)));
            unsigned int dd3 = h2u(__hadd2(u2h(qd.w), u2h(ndi2)));
            unsigned int de0 = h2u(__hadd2(u2h(ei2), u2h(qe.x)));
            unsigned int de1 = h2u(__hadd2(u2h(ei2), u2h(qe.y)));
            unsigned int de2 = h2u(__hadd2(u2h(ei2), u2h(qe.z)));
            unsigned int de3 = h2u(__hadd2(u2h(ei2), u2h(qe.w)));
            a0 = __hadd2(a0, __hmax2(u2h(sflip2(de0, dd0)), neg1));
            a1 = __hadd2(a1, __hmax2(u2h(sflip2(de1, dd1)), neg1));
            a2 = __hadd2(a2, __hmax2(u2h(sflip2(de2, dd2)), neg1));
            a3 = __hadd2(a3, __hmax2(u2h(sflip2(de3, dd3)), neg1));
            qd = nd; qe = ne;
        }
        float2 f0 = __half22float2(a0), f1 = __half22float2(a1);
        float2 f2 = __half22float2(a2), f3 = __half22float2(a3);
        facc += ((f0.x + f0.y) + (f1.x + f1.y))
              + ((f2.x + f2.y) + (f3.x + f3.y));
    }

    // diagonal brick counted every unordered pair twice (self-pairs = 0)
    if (diag) facc *= 0.5f;

    // --- block reduction ---
    #pragma unroll
    for (int o = 16; o > 0; o >>= 1)
        facc += __shfl_down_sync(0xFFFFFFFFu, facc, o);

    int w = t >> 5, l = t & 31;
    if (l == 0) ssum[w] = facc;
    __syncthreads();

    // --- spread global accumulation + last-block epilogue ---
    if (t == 0) {
        float a = 0.0f;
        #pragma unroll
        for (int k = 0; k < THREADS / 32; k++) a += ssum[k];
        atomicAdd(&g_sum[bid & 7], (double)a);     // 8 slots -> no burst
        __threadfence();
        unsigned int old = atomicInc(&g_tick, (unsigned int)(NB - 1));
        if (old == (unsigned int)(NB - 1)) {
            __threadfence();
            double tot = 0.0;
            #pragma unroll
            for (int k = 0; k < 8; k++) {
                unsigned long long b =
                    atomicExch((unsigned long long*)&g_sum[k], 0ull);
                tot += __longlong_as_double(b);    // read + reset (replayable)
            }
            out[0] = (float)((tot + nslots) * invcnt);
        }
    }
}

// ---------------------------------------------------------------------------
extern "C" void kernel_launch(void* const* d_in, const int* in_sizes, int n_in,
                              void* d_out, int out_size) {
    const float* energies = (const float*)d_in[0];   // (B, 1)
    const float* pv       = (const float*)d_in[1];   // (B, P)
    const float* pt       = (const float*)d_in[2];   // (P,)
    float* out            = (float*)d_out;

    int B = in_sizes[0];
    int P = in_sizes[2];

    int T  = (B + TILE - 1) / TILE;
    int NB = T * (T + 1) / 2;

    // exact +1-per-slot total (unordered slots):
    //   off-diag bricks: TILE*TILE each; diag: TILE*(TILE-1)/2 each;
    //   pad rows net 0 except pad-pad slots (value 0 but +1) -> subtract.
    double npad = (double)(T * TILE - B);
    double nslots = (double)(T * (T - 1) / 2) * (double)TILE * (double)TILE
                  + (double)T * (double)((long long)TILE * (TILE - 1) / 2)
                  - npad * (npad - 1.0) * 0.5;

    double cnt = (double)B * (double)(B - 1) * 0.5;
    if (cnt < 1.0) cnt = 1.0;

    fused_kernel<<<NB, THREADS>>>(energies, pv, pt, B, P, T, NB,
                                  nslots, 1.0 / cnt, out);
}